// round 3
// baseline (speedup 1.0000x reference)
#include <cuda_runtime.h>
#include <math.h>

#define BATCH 32
#define NPTS  512
#define NN    (BATCH*NPTS)     // 16384
#define ND    128
#define F0D   384
#define CATD  1152
#define HROWS 513

// ---------------- scratch (device globals; no allocation allowed) ----------------
__device__ float g_L  [(size_t)BATCH*NPTS*NPTS];   // A then L, in place
__device__ float g_G  [(size_t)NN*CATD];           // [F0 | F0^2 | F0^3]
__device__ float g_LG [(size_t)NN*CATD];
__device__ float g_LLG[(size_t)NN*CATD];
__device__ float g_F1 [(size_t)NN*F0D];            // pre-BN F1 (after leaky+residual)
__device__ float g_X  [NN*3];
__device__ float g_deg[NN];
__device__ float g_bnsum[F0D];
__device__ float g_bnsq [F0D];
__device__ float g_scale[F0D];
__device__ float g_colbias[ND];
__device__ unsigned g_dlmax_bits;
__device__ unsigned g_amax_bits;

// ---------------- small kernels ----------------
__global__ void init_k() {
    if (threadIdx.x == 0) { g_dlmax_bits = 0u; g_amax_bits = 0u; }
}

__global__ void dlmax_k(const float* __restrict__ dl) {
    int i = blockIdx.x * blockDim.x + threadIdx.x;     // exactly NN threads
    float v = dl[i];
    #pragma unroll
    for (int o = 16; o; o >>= 1) v = fmaxf(v, __shfl_xor_sync(0xffffffff, v, o));
    if ((threadIdx.x & 31) == 0) atomicMax(&g_dlmax_bits, __float_as_uint(v));
}

__global__ void x_k(const float* __restrict__ loc, const float* __restrict__ dl) {
    int i = blockIdx.x * blockDim.x + threadIdx.x;
    if (i >= NN) return;
    float inv = 1.0f / __uint_as_float(g_dlmax_bits);
    g_X[i*3+0] = loc[i*2+0];
    g_X[i*3+1] = loc[i*2+1];
    g_X[i*3+2] = dl[i] * inv;
}

// A[b,i,j] = (i==j) ? 0 : 1/dist; track global max. 32x32 tiles.
__global__ void a_k() {
    int b  = blockIdx.z;
    int i0 = blockIdx.y * 32, j0 = blockIdx.x * 32;
    __shared__ float Xi[32][3], Xj[32][3];
    int t = threadIdx.x;                       // 256
    if (t < 96)       ((float*)Xi)[t]      = g_X[((size_t)b*NPTS + i0)*3 + t];
    else if (t < 192) ((float*)Xj)[t-96]   = g_X[((size_t)b*NPTS + j0)*3 + (t-96)];
    __syncthreads();
    int tx = t & 31, ty = t >> 5;              // ty 0..7
    float xj0 = Xj[tx][0], xj1 = Xj[tx][1], xj2 = Xj[tx][2];
    float m = 0.0f;
    float* Ab = g_L + (size_t)b * NPTS * NPTS;
    #pragma unroll
    for (int r = 0; r < 4; r++) {
        int i = ty * 4 + r;
        float dx = Xi[i][0]-xj0, dy = Xi[i][1]-xj1, dz = Xi[i][2]-xj2;
        float d2 = dx*dx + dy*dy + dz*dz;
        float v  = (i0 + i == j0 + tx) ? 0.0f : rsqrtf(d2);
        Ab[(size_t)(i0+i)*NPTS + j0 + tx] = v;
        m = fmaxf(m, v);
    }
    #pragma unroll
    for (int o = 16; o; o >>= 1) m = fmaxf(m, __shfl_xor_sync(0xffffffff, m, o));
    __shared__ float wm[8];
    if (tx == 0) wm[ty] = m;
    __syncthreads();
    if (t == 0) {
        float mm = wm[0];
        #pragma unroll
        for (int w = 1; w < 8; w++) mm = fmaxf(mm, wm[w]);
        atomicMax(&g_amax_bits, __float_as_uint(mm));
    }
}

// deg[row] = rowsum(A)/Amax - 1 ; one warp per row
__global__ void deg_k() {
    int gw   = (blockIdx.x * blockDim.x + threadIdx.x) >> 5;
    int lane = threadIdx.x & 31;
    if (gw >= NN) return;
    const float4* row = (const float4*)(g_L + (size_t)gw * NPTS);
    float s = 0.0f;
    #pragma unroll
    for (int w = 0; w < 4; w++) { float4 v = row[lane + w*32]; s += v.x+v.y+v.z+v.w; }
    #pragma unroll
    for (int o = 16; o; o >>= 1) s += __shfl_xor_sync(0xffffffff, s, o);
    if (lane == 0) g_deg[gw] = s / __uint_as_float(g_amax_bits) - 1.0f;
}

// L = diag(deg) - A/Amax, in place
__global__ void l_k() {
    size_t idx = (size_t)blockIdx.x * blockDim.x + threadIdx.x;
    if (idx >= (size_t)BATCH*NPTS*NPTS) return;
    float inv = 1.0f / __uint_as_float(g_amax_bits);
    int    j  = (int)(idx & 511);
    size_t r  = idx >> 9;                    // global row 0..16383
    int    i  = (int)(r & 511);
    float v = -g_L[idx] * inv;
    if (i == j) v += g_deg[r];
    g_L[idx] = v;
}

// G = [F0 | F0^2 | F0^3], F0 = X @ W_init + b_init
__global__ void g0_k(const float* __restrict__ Wi, const float* __restrict__ bi) {
    int t = blockIdx.x * blockDim.x + threadIdx.x;
    if (t >= NN * F0D) return;
    int row = t / F0D, j = t - row * F0D;
    const float* x = &g_X[row*3];
    float f = fmaf(x[0], Wi[j], fmaf(x[1], Wi[F0D+j], fmaf(x[2], Wi[2*F0D+j], bi[j])));
    size_t base = (size_t)row * CATD;
    g_G[base + j]         = f;
    g_G[base + F0D + j]   = f*f;
    g_G[base + 2*F0D + j] = f*f*f;
}

// ---------------- batched SGEMM: C = L @ B  ([512,512]@[512,1152] x32) ----------------
// mode 0: B=g_G  -> C=g_LG ;  mode 1: B=g_LG -> C=g_LLG
__global__ void __launch_bounds__(256) sgemm_k(int mode) {
    const float* A = g_L + (size_t)blockIdx.z * NPTS * NPTS;
    const float* B = (mode ? g_LG : g_G)  + (size_t)blockIdx.z * NPTS * CATD;
    float*       C = (mode ? g_LLG: g_LG) + (size_t)blockIdx.z * NPTS * CATD;
    int bm = blockIdx.y * 128, bn = blockIdx.x * 128;
    __shared__ float As[8][128], Bs[8][128];
    int t = threadIdx.x;
    int arow = t >> 1, acol = (t & 1) * 4;
    int brow = t >> 5, bcol = (t & 31) * 4;
    int tx = t & 15, ty = t >> 4;
    float acc[8][8] = {};
    const float* Aptr = A + (size_t)(bm + arow) * NPTS + acol;
    const float* Bptr = B + (size_t)brow * CATD + bn + bcol;
    for (int k0 = 0; k0 < NPTS; k0 += 8) {
        float4 av = *(const float4*)(Aptr + k0);
        float4 bv = *(const float4*)(Bptr + (size_t)k0 * CATD);
        As[acol+0][arow] = av.x; As[acol+1][arow] = av.y;
        As[acol+2][arow] = av.z; As[acol+3][arow] = av.w;
        *(float4*)&Bs[brow][bcol] = bv;
        __syncthreads();
        #pragma unroll
        for (int kk = 0; kk < 8; kk++) {
            float ra[8], rb[8];
            *(float4*)(ra)   = *(float4*)&As[kk][ty*4];
            *(float4*)(ra+4) = *(float4*)&As[kk][64 + ty*4];
            *(float4*)(rb)   = *(float4*)&Bs[kk][tx*4];
            *(float4*)(rb+4) = *(float4*)&Bs[kk][64 + tx*4];
            #pragma unroll
            for (int i = 0; i < 8; i++)
                #pragma unroll
                for (int j = 0; j < 8; j++) acc[i][j] = fmaf(ra[i], rb[j], acc[i][j]);
        }
        __syncthreads();
    }
    #pragma unroll
    for (int i = 0; i < 8; i++) {
        int r = bm + ((i < 4) ? ty*4 + i : 64 + ty*4 + (i-4));
        float* crow = C + (size_t)r * CATD + bn;
        *(float4*)(crow + tx*4)      = *(float4*)&acc[i][0];
        *(float4*)(crow + 64 + tx*4) = *(float4*)&acc[i][4];
    }
}

// ---------------- g-projection GEMM + fused epilogue ----------------
// out block kb (0..2): F1[:,kb*128+c] = leaky( sum_p slice_p @ Wg[kb] + bg ) + F0
__global__ void __launch_bounds__(256) ggemm_k(
    const float* __restrict__ Wg1, const float* __restrict__ Wg2, const float* __restrict__ Wg3,
    const float* __restrict__ bg1, const float* __restrict__ bg2, const float* __restrict__ bg3)
{
    int bm = blockIdx.x * 128;
    int kb = blockIdx.y;                                   // 0..2
    const float* Wg = (kb == 0) ? Wg1 : (kb == 1 ? Wg2 : Wg3);
    const float* bg = (kb == 0) ? bg1 : (kb == 1 ? bg2 : bg3);
    __shared__ float As[8][128], Bs[8][128];
    int t = threadIdx.x;
    int arow = t >> 1, acol = (t & 1) * 4;
    int brow = t >> 5, bcol = (t & 31) * 4;
    int tx = t & 15, ty = t >> 4;
    float acc[8][8] = {};
    #pragma unroll
    for (int p = 0; p < 3; p++) {
        const float* src  = (p == 0) ? g_G : (p == 1 ? g_LG : g_LLG);
        const float* Aptr = src + (size_t)(bm + arow) * CATD + kb * F0D + acol;
        const float* Bptr = Wg + (size_t)(p * F0D + brow) * ND + bcol;
        for (int k0 = 0; k0 < F0D; k0 += 8) {
            float4 av = *(const float4*)(Aptr + k0);
            float4 bv = *(const float4*)(Bptr + (size_t)k0 * ND);
            As[acol+0][arow] = av.x; As[acol+1][arow] = av.y;
            As[acol+2][arow] = av.z; As[acol+3][arow] = av.w;
            *(float4*)&Bs[brow][bcol] = bv;
            __syncthreads();
            #pragma unroll
            for (int kk = 0; kk < 8; kk++) {
                float ra[8], rb[8];
                *(float4*)(ra)   = *(float4*)&As[kk][ty*4];
                *(float4*)(ra+4) = *(float4*)&As[kk][64 + ty*4];
                *(float4*)(rb)   = *(float4*)&Bs[kk][tx*4];
                *(float4*)(rb+4) = *(float4*)&Bs[kk][64 + tx*4];
                #pragma unroll
                for (int i = 0; i < 8; i++)
                    #pragma unroll
                    for (int j = 0; j < 8; j++) acc[i][j] = fmaf(ra[i], rb[j], acc[i][j]);
            }
            __syncthreads();
        }
    }
    // epilogue: bias -> leaky_relu -> +F0 residual -> store F1
    #pragma unroll
    for (int i = 0; i < 8; i++) {
        int r = bm + ((i < 4) ? ty*4 + i : 64 + ty*4 + (i-4));
        #pragma unroll
        for (int jj = 0; jj < 8; jj++) {
            int c = (jj < 4) ? tx*4 + jj : 64 + tx*4 + (jj-4);
            float v = acc[i][jj] + bg[c];
            v = (v > 0.0f) ? v : 0.01f * v;
            v += g_G[(size_t)r * CATD + kb * 128 + c];     // F0 residual
            g_F1[(size_t)r * F0D + kb * 128 + c] = v;
        }
    }
}

// ---------------- deterministic BN stats (one block per channel) ----------------
__global__ void bnstat_k() {
    int c = blockIdx.x, t = threadIdx.x;                   // 256 threads
    float s = 0.0f, q = 0.0f;
    for (int r = t; r < NN; r += 256) {
        float v = g_F1[(size_t)r * F0D + c];
        s += v; q += v * v;
    }
    __shared__ float sh[256], sh2[256];
    sh[t] = s; sh2[t] = q; __syncthreads();
    for (int o = 128; o; o >>= 1) {
        if (t < o) { sh[t] += sh[t+o]; sh2[t] += sh2[t+o]; }
        __syncthreads();
    }
    if (t == 0) { g_bnsum[c] = sh[0]; g_bnsq[c] = sh2[0]; }
}

// BN scale/shift; fold shift^T @ W_F + b_F into per-column bias
__global__ void bnfin_k(const float* __restrict__ gamma, const float* __restrict__ beta,
                        const float* __restrict__ WF,    const float* __restrict__ bF) {
    __shared__ float sh[F0D];
    int t = threadIdx.x;                                   // 384 threads
    float mu   = g_bnsum[t] * (1.0f / NN);
    float var  = g_bnsq[t]  * (1.0f / NN) - mu * mu;
    float istd = rsqrtf(var + 1e-5f);
    float sc   = gamma[t] * istd;
    g_scale[t] = sc;
    sh[t]      = beta[t] - mu * sc;
    __syncthreads();
    if (t < ND) {
        float s = bF[t];
        for (int k = 0; k < F0D; k++) s = fmaf(sh[k], WF[(size_t)k * ND + t], s);
        g_colbias[t] = s;
    }
}

// ---------------- final GEMM: leaky((F1*scale)@W_F + colbias) -> h rows 1..512 ----------------
__global__ void __launch_bounds__(256) fgemm_k(const float* __restrict__ WF, float* __restrict__ out) {
    int bm = blockIdx.x * 128;
    __shared__ float As[8][128], Bs[8][128];
    int t = threadIdx.x;
    int arow = t >> 1, acol = (t & 1) * 4;
    int brow = t >> 5, bcol = (t & 31) * 4;
    int tx = t & 15, ty = t >> 4;
    float acc[8][8] = {};
    const float* Aptr = g_F1 + (size_t)(bm + arow) * F0D + acol;
    for (int k0 = 0; k0 < F0D; k0 += 8) {
        float4 av = *(const float4*)(Aptr + k0);
        float4 sc = *(const float4*)&g_scale[k0 + acol];
        av.x *= sc.x; av.y *= sc.y; av.z *= sc.z; av.w *= sc.w;
        float4 bv = *(const float4*)(WF + (size_t)(k0 + brow) * ND + bcol);
        As[acol+0][arow] = av.x; As[acol+1][arow] = av.y;
        As[acol+2][arow] = av.z; As[acol+3][arow] = av.w;
        *(float4*)&Bs[brow][bcol] = bv;
        __syncthreads();
        #pragma unroll
        for (int kk = 0; kk < 8; kk++) {
            float ra[8], rb[8];
            *(float4*)(ra)   = *(float4*)&As[kk][ty*4];
            *(float4*)(ra+4) = *(float4*)&As[kk][64 + ty*4];
            *(float4*)(rb)   = *(float4*)&Bs[kk][tx*4];
            *(float4*)(rb+4) = *(float4*)&Bs[kk][64 + tx*4];
            #pragma unroll
            for (int i = 0; i < 8; i++)
                #pragma unroll
                for (int j = 0; j < 8; j++) acc[i][j] = fmaf(ra[i], rb[j], acc[i][j]);
        }
        __syncthreads();
    }
    #pragma unroll
    for (int i = 0; i < 8; i++) {
        int r    = bm + ((i < 4) ? ty*4 + i : 64 + ty*4 + (i-4));
        int b    = r >> 9;
        int nloc = r & 511;
        float* orow = out + ((size_t)b * HROWS + 1 + nloc) * ND;
        float v4[8];
        #pragma unroll
        for (int jj = 0; jj < 8; jj++) {
            int c = (jj < 4) ? tx*4 + jj : 64 + tx*4 + (jj-4);
            float v = acc[i][jj] + g_colbias[c];
            v4[jj] = (v > 0.0f) ? v : 0.01f * v;
        }
        *(float4*)(orow + tx*4)      = *(float4*)&v4[0];
        *(float4*)(orow + 64 + tx*4) = *(float4*)&v4[4];
    }
}

// depot row: h[b,0,:] = depot[b] @ W_dep + b_dep
__global__ void dep_k(const float* __restrict__ depot, const float* __restrict__ Wd,
                      const float* __restrict__ bd, float* __restrict__ out) {
    int b = blockIdx.x, t = threadIdx.x;                   // 32 x 128
    out[(size_t)b * HROWS * ND + t] =
        fmaf(depot[b*2+0], Wd[t], fmaf(depot[b*2+1], Wd[ND + t], bd[t]));
}

// mean over the 513 rows of h per batch
__global__ void mean_k(float* __restrict__ out) {
    int b = blockIdx.x, t = threadIdx.x;                   // 32 x 128
    const float* base = out + (size_t)b * HROWS * ND + t;
    float s = 0.0f;
    for (int r = 0; r < HROWS; r++) s += base[(size_t)r * ND];
    out[(size_t)BATCH * HROWS * ND + (size_t)b * ND + t] = s * (1.0f / HROWS);
}

// ---------------- launch ----------------
extern "C" void kernel_launch(void* const* d_in, const int* in_sizes, int n_in,
                              void* d_out, int out_size) {
    const float* loc   = (const float*)d_in[0];
    const float* dl    = (const float*)d_in[1];
    // d_in[2] = workload (unused by the reference)
    const float* depot = (const float*)d_in[3];
    const float* Wi    = (const float*)d_in[4];
    const float* bi    = (const float*)d_in[5];
    const float* Wd    = (const float*)d_in[6];
    const float* bd    = (const float*)d_in[7];
    const float* Wg1   = (const float*)d_in[8];
    const float* bg1   = (const float*)d_in[9];
    const float* Wg2   = (const float*)d_in[10];
    const float* bg2   = (const float*)d_in[11];
    const float* Wg3   = (const float*)d_in[12];
    const float* bg3   = (const float*)d_in[13];
    const float* gamma = (const float*)d_in[14];
    const float* beta  = (const float*)d_in[15];
    const float* WF    = (const float*)d_in[16];
    const float* bF    = (const float*)d_in[17];
    float* out = (float*)d_out;

    init_k <<<1, 64>>>();
    dlmax_k<<<NN/256, 256>>>(dl);
    x_k    <<<(NN+255)/256, 256>>>(loc, dl);
    a_k    <<<dim3(16, 16, BATCH), 256>>>();
    deg_k  <<<NN/8, 256>>>();
    l_k    <<<(int)(((size_t)BATCH*NPTS*NPTS + 255)/256), 256>>>();
    g0_k   <<<(NN*F0D + 255)/256, 256>>>(Wi, bi);
    sgemm_k<<<dim3(CATD/128, NPTS/128, BATCH), 256>>>(0);   // LG  = L @ G
    sgemm_k<<<dim3(CATD/128, NPTS/128, BATCH), 256>>>(1);   // LLG = L @ LG
    ggemm_k<<<dim3(NN/128, 3), 256>>>(Wg1, Wg2, Wg3, bg1, bg2, bg3);
    bnstat_k<<<F0D, 256>>>();
    bnfin_k<<<1, F0D>>>(gamma, beta, WF, bF);
    fgemm_k<<<NN/128, 256>>>(WF, out);
    dep_k  <<<BATCH, ND>>>(depot, Wd, bd, out);
    mean_k <<<BATCH, ND>>>(out);
}